// round 16
// baseline (speedup 1.0000x reference)
#include <cuda_runtime.h>
#include <cuda_bf16.h>
#include <math.h>
#include <float.h>

#define BATCH 2
#define NPTS  8192
#define KNB   16
#define NSEG  256
#define DIM   768
#define H1DIM 128
#define H2DIM 256

typedef unsigned long long u64;

// ---------------- f32x2 helpers (gemm_pc) ----------------
__device__ __forceinline__ void ffma2(u64& d, u64 a, u64 b) {
    asm("fma.rn.f32x2 %0, %1, %2, %0;" : "+l"(d) : "l"(a), "l"(b));
}
__device__ __forceinline__ u64 pack2(float lo, float hi) {
    u64 r; asm("mov.b64 %0, {%1, %2};" : "=l"(r) : "f"(lo), "f"(hi)); return r;
}
__device__ __forceinline__ void unpack2(u64 v, float& lo, float& hi) {
    asm("mov.b64 {%0, %1}, %2;" : "=f"(lo), "=f"(hi) : "l"(v));
}

// ---------------- HMMA helpers (standard sm_80+ PTX, no arch feature gates) ----------------
__device__ __forceinline__ unsigned smem_u32(const void* p) {
    unsigned a;
    asm("{ .reg .u64 t; cvta.to.shared.u64 t, %1; cvt.u32.u64 %0, t; }" : "=r"(a) : "l"(p));
    return a;
}
__device__ __forceinline__ void ldsm4(unsigned addr, unsigned r[4]) {
    asm volatile("ldmatrix.sync.aligned.m8n8.x4.shared.b16 {%0,%1,%2,%3}, [%4];"
                 : "=r"(r[0]), "=r"(r[1]), "=r"(r[2]), "=r"(r[3]) : "r"(addr));
}
__device__ __forceinline__ void mma16816(float d[4], const unsigned a[4],
                                         unsigned b0, unsigned b1) {
    asm volatile(
        "mma.sync.aligned.m16n8k16.row.col.f32.bf16.bf16.f32 "
        "{%0,%1,%2,%3},{%4,%5,%6,%7},{%8,%9},{%0,%1,%2,%3};"
        : "+f"(d[0]), "+f"(d[1]), "+f"(d[2]), "+f"(d[3])
        : "r"(a[0]), "r"(a[1]), "r"(a[2]), "r"(a[3]), "r"(b0), "r"(b1));
}

// ---------------- device scratch ----------------
static __device__ float4 g_c4[BATCH * NPTS];
static __device__ int    g_idx[BATCH * NPTS * KNB];
static __device__ __align__(16) float g_hbar[BATCH * NPTS * H2DIM];
static __device__ float  g_sums[BATCH * NSEG * DIM];
static __device__ float  g_counts[BATCH * NSEG];
static __device__ float  g_means[BATCH * NSEG * DIM];
static __device__ float  g_lin1[BATCH * NSEG * DIM];
static __device__ float  g_lnr[BATCH * NSEG * DIM];
static __device__ float  g_agg[BATCH * NSEG * DIM];
// W2 split to bf16 hi/lo, transposed [n][k]
static __device__ __align__(16) __nv_bfloat16 g_w2h[H2DIM * H1DIM];
static __device__ __align__(16) __nv_bfloat16 g_w2l[H2DIM * H1DIM];

// ---------------- prep kernels ----------------
__global__ void prep_kernel(const float* __restrict__ coords) {
    int i = blockIdx.x * 256 + threadIdx.x;
    if (i < BATCH * NSEG * DIM) g_sums[i] = 0.0f;
    if (i < BATCH * NSEG) g_counts[i] = 0.0f;
    if (i < BATCH * NPTS) {
        float x = coords[3 * i + 0];
        float y = coords[3 * i + 1];
        float z = coords[3 * i + 2];
        g_c4[i] = make_float4(x, y, z, x * x + y * y + z * z);
    }
}

__global__ void count_kernel(const int* __restrict__ labels) {
    int i = blockIdx.x * 256 + threadIdx.x;
    if (i >= BATCH * NPTS) return;
    atomicAdd(&g_counts[(i >> 13) * NSEG + labels[i]], 1.0f);
}

// split W2 (fp32 [k][n]) into bf16 hi/lo, transposed to [n][k]
__global__ void w2split_kernel(const float* __restrict__ W2) {
    int i = blockIdx.x * 256 + threadIdx.x;
    if (i >= H2DIM * H1DIM) return;
    int n = i >> 7, k = i & 127;
    float v = W2[k * H2DIM + n];
    __nv_bfloat16 h = __float2bfloat16(v);
    g_w2h[i] = h;
    g_w2l[i] = __float2bfloat16(v - __bfloat162float(h));
}

// ---------------- KNN: warp-cooperative sorted queue + ballot collect ----------------
__global__ void knn_kernel() {
    __shared__ float4 tile[2048];
    int b = blockIdx.y;
    int warp = threadIdx.x >> 5;
    int lane = threadIdx.x & 31;
    int q = blockIdx.x * 8 + warp;

    float4 qc = g_c4[b * NPTS + q];
    float ax = -2.0f * qc.x, ay = -2.0f * qc.y, az = -2.0f * qc.z;

    const float INF  = __int_as_float(0x7f800000);
    const float NINF = __int_as_float(0xff800000);
    float S = INF;
    float thresh = INF;

    for (int t = 0; t < 4; t++) {
        __syncthreads();
        for (int i = threadIdx.x; i < 2048; i += 256)
            tile[i] = g_c4[b * NPTS + t * 2048 + i];
        __syncthreads();
#pragma unroll 4
        for (int it = 0; it < 64; it++) {
            float4 c = tile[it * 32 + lane];
            float key = fmaf(ax, c.x, fmaf(ay, c.y, fmaf(az, c.z, c.w)));
            unsigned ball = __ballot_sync(0xffffffffu, key < thresh);
            while (ball) {
                int src = __ffs(ball) - 1;
                ball &= ball - 1;
                float k = __shfl_sync(0xffffffffu, key, src);
                float up = __shfl_up_sync(0xffffffffu, S, 1);
                if (lane == 0) up = NINF;
                S = (S < k) ? S : fmaxf(k, up);
                thresh = __shfl_sync(0xffffffffu, S, 15);
            }
        }
    }

    int cnt = 0;
    int base = (b * NPTS + q) * KNB;
    for (int t = 0; t < 4; t++) {
        __syncthreads();
        for (int i = threadIdx.x; i < 2048; i += 256)
            tile[i] = g_c4[b * NPTS + t * 2048 + i];
        __syncthreads();
#pragma unroll 4
        for (int it = 0; it < 64; it++) {
            float4 c = tile[it * 32 + lane];
            float key = fmaf(ax, c.x, fmaf(ay, c.y, fmaf(az, c.z, c.w)));
            bool p = (key <= thresh);
            unsigned ball = __ballot_sync(0xffffffffu, p);
            if (p) {
                int pos = cnt + __popc(ball & ((1u << lane) - 1u));
                if (pos < KNB) g_idx[base + pos] = t * 2048 + it * 32 + lane;
            }
            cnt += __popc(ball);
        }
    }
}

// ---------------- mlp12 via HMMA (mma.sync bf16 split) ----------------
// block = 512 threads (16 warps), 8 points = 128 rows; cols = 256; K = 128.
// warp: rg = wid&7 (one point, rows rg*16..+15), cg = wid>>3 (cols cg*128..+127).
// dynamic smem: h1h 32KB | h1l 32KB | w2h chunk 8KB | w2l chunk 8KB  (=81920 B)
__global__ void __launch_bounds__(512, 1)
mlp12h_kernel(const float* __restrict__ W1, const float* __restrict__ b1,
              const float* __restrict__ b2) {
    extern __shared__ __align__(16) char dsm[];
    char* h1h = dsm;                 // [128 rows][128 k] bf16, 256 B/row
    char* h1l = dsm + 32768;
    char* w2h = dsm + 65536;         // [256 n][16 k] bf16, 32 B/row
    char* w2l = dsm + 73728;
    __shared__ float w1s[7 * H1DIM];
    __shared__ float b1s[H1DIM];
    __shared__ float b2s[H2DIM];

    int tid = threadIdx.x;
    int wid = tid >> 5;
    int lane = tid & 31;
    int blk = blockIdx.x;
    int rg = wid & 7, cg = wid >> 3;

    for (int i = tid; i < 7 * H1DIM; i += 512) w1s[i] = W1[i];
    if (tid < H1DIM) b1s[tid] = b1[tid];
    if (tid < H2DIM) b2s[tid] = b2[tid];
    __syncthreads();

    // ---- phase 1: features + layer1 -> bf16 hi/lo smem ----
    {
        int row = tid >> 2;          // 0..127
        int qq  = tid & 3;           // channel quarter (32 ch)
        int pg  = blk * 8 + (row >> 4);
        int bb  = pg >> 13;
        int k   = row & 15;
        int nb  = g_idx[pg * KNB + k];
        float4 sc = g_c4[pg];
        float4 nc = g_c4[bb * NPTS + nb];
        float dx = nc.x - sc.x, dy = nc.y - sc.y, dz = nc.z - sc.z;
        float f0 = sqrtf(dx * dx + dy * dy + dz * dz);
        float f4 = atan2f(dy, dx);
        float f5 = atan2f(dz, dx);
        float f6 = atan2f(dz, dy);
        unsigned* h1hw = (unsigned*)(h1h + row * 256 + qq * 64);
        unsigned* h1lw = (unsigned*)(h1l + row * 256 + qq * 64);
#pragma unroll
        for (int t = 0; t < 16; t++) {
            int c = qq * 32 + 2 * t;
            float a0 = b1s[c], a1 = b1s[c + 1];
            a0 = fmaf(f0, w1s[c], a0);               a1 = fmaf(f0, w1s[c + 1], a1);
            a0 = fmaf(dx, w1s[H1DIM + c], a0);       a1 = fmaf(dx, w1s[H1DIM + c + 1], a1);
            a0 = fmaf(dy, w1s[2 * H1DIM + c], a0);   a1 = fmaf(dy, w1s[2 * H1DIM + c + 1], a1);
            a0 = fmaf(dz, w1s[3 * H1DIM + c], a0);   a1 = fmaf(dz, w1s[3 * H1DIM + c + 1], a1);
            a0 = fmaf(f4, w1s[4 * H1DIM + c], a0);   a1 = fmaf(f4, w1s[4 * H1DIM + c + 1], a1);
            a0 = fmaf(f5, w1s[5 * H1DIM + c], a0);   a1 = fmaf(f5, w1s[5 * H1DIM + c + 1], a1);
            a0 = fmaf(f6, w1s[6 * H1DIM + c], a0);   a1 = fmaf(f6, w1s[6 * H1DIM + c + 1], a1);
            a0 = fmaxf(a0, 0.0f); a1 = fmaxf(a1, 0.0f);
            __nv_bfloat16 h0 = __float2bfloat16(a0), h1 = __float2bfloat16(a1);
            float r0 = a0 - __bfloat162float(h0), r1 = a1 - __bfloat162float(h1);
            __nv_bfloat16 l0 = __float2bfloat16(r0), l1 = __float2bfloat16(r1);
            h1hw[t] = ((unsigned)__bfloat16_as_ushort(h1) << 16) | (unsigned)__bfloat16_as_ushort(h0);
            h1lw[t] = ((unsigned)__bfloat16_as_ushort(l1) << 16) | (unsigned)__bfloat16_as_ushort(l0);
        }
    }

    // ---- phase 2: D = Ah*Bh + Ah*Bl + Al*Bh over K=128 (8 chunks of 16) ----
    float d[16][4];
#pragma unroll
    for (int nt = 0; nt < 16; nt++)
#pragma unroll
        for (int j = 0; j < 4; j++) d[nt][j] = 0.0f;

    unsigned h1h_b = smem_u32(h1h), h1l_b = smem_u32(h1l);
    unsigned w2h_b = smem_u32(w2h), w2l_b = smem_u32(w2l);

    int rbase = rg * 16;
    unsigned arow = (unsigned)(rbase + (lane & 15));
    unsigned akoff = (unsigned)((lane >> 4) << 3);
    unsigned brow = (unsigned)(cg * 128 + (lane & 7) + ((lane >> 4) << 3));
    unsigned bkoff = (unsigned)(((lane >> 3) & 1) << 3);

    for (int ks = 0; ks < 8; ks++) {
        __syncthreads();
        // stage W2 chunk [256n][16k] hi+lo
        {
            int n = tid >> 1, half = tid & 1;
            const uint4* sh = (const uint4*)(g_w2h + n * H1DIM + ks * 16 + half * 8);
            const uint4* sl = (const uint4*)(g_w2l + n * H1DIM + ks * 16 + half * 8);
            ((uint4*)w2h)[n * 2 + half] = *sh;
            ((uint4*)w2l)[n * 2 + half] = *sl;
        }
        __syncthreads();

        unsigned ah[4], al[4];
        unsigned aaddr = arow * 256u + (unsigned)(ks * 16) * 2u + akoff * 2u;
        ldsm4(h1h_b + aaddr, ah);
        ldsm4(h1l_b + aaddr, al);

#pragma unroll
        for (int i = 0; i < 8; i++) {
            unsigned bh[4], bl[4];
            unsigned baddr = (brow + (unsigned)(i * 16)) * 32u + bkoff * 2u;
            ldsm4(w2h_b + baddr, bh);
            ldsm4(w2l_b + baddr, bl);
            mma16816(d[2 * i],     ah, bh[0], bh[1]);
            mma16816(d[2 * i],     ah, bl[0], bl[1]);
            mma16816(d[2 * i],     al, bh[0], bh[1]);
            mma16816(d[2 * i + 1], ah, bh[2], bh[3]);
            mma16816(d[2 * i + 1], ah, bl[2], bl[3]);
            mma16816(d[2 * i + 1], al, bh[2], bh[3]);
        }
    }

    // ---- epilogue: bias + relu, mean over the point's 16 rows ----
    int p = blk * 8 + rg;
    const float inv16 = 1.0f / 16.0f;
#pragma unroll
    for (int nt = 0; nt < 16; nt++) {
        int ncol = cg * 128 + nt * 8 + 2 * (lane & 3);
        float bv0 = b2s[ncol], bv1 = b2s[ncol + 1];
        float s0 = fmaxf(d[nt][0] + bv0, 0.0f) + fmaxf(d[nt][2] + bv0, 0.0f);
        float s1 = fmaxf(d[nt][1] + bv1, 0.0f) + fmaxf(d[nt][3] + bv1, 0.0f);
        s0 += __shfl_xor_sync(0xffffffffu, s0, 4);
        s0 += __shfl_xor_sync(0xffffffffu, s0, 8);
        s0 += __shfl_xor_sync(0xffffffffu, s0, 16);
        s1 += __shfl_xor_sync(0xffffffffu, s1, 4);
        s1 += __shfl_xor_sync(0xffffffffu, s1, 8);
        s1 += __shfl_xor_sync(0xffffffffu, s1, 16);
        if (lane < 4) {
            int col = cg * 128 + nt * 8 + 2 * lane;
            g_hbar[p * H2DIM + col]     = s0 * inv16;
            g_hbar[p * H2DIM + col + 1] = s1 * inv16;
        }
    }
}

// ---------------- gemm_pc: pc = hbar @ W3 + b3, FFMA2 8x8, fused scatter ----------------
__global__ void __launch_bounds__(256, 2)
gemm_pc_kernel(const float* __restrict__ W3, const float* __restrict__ b3,
               const int* __restrict__ labels, float* __restrict__ out) {
    __shared__ __align__(16) float As[16 * 64];
    __shared__ __align__(16) float Bs[16 * 256];
    __shared__ int   lbls[64];
    __shared__ float b3s[256];
    int tid = threadIdx.x;
    int r0 = blockIdx.y * 64;
    int c0 = blockIdx.x * 256;

    if (tid < 64) lbls[tid] = labels[r0 + tid];
    b3s[tid] = b3[c0 + tid];

    int lane = tid & 31, w = tid >> 5;
    int rg  = lane >> 2;
    int cgl = lane & 3;
    int cg  = w * 4 + cgl;

    u64 acc2[8][4];
#pragma unroll
    for (int r = 0; r < 8; r++)
#pragma unroll
        for (int j = 0; j < 4; j++) acc2[r][j] = 0ull;

    int arow = tid & 63, akq = tid >> 6;
    for (int k0 = 0; k0 < H2DIM; k0 += 16) {
        __syncthreads();
        {
            float4 av = *(const float4*)&g_hbar[(r0 + arow) * H2DIM + k0 + akq * 4];
            As[(akq * 4 + 0) * 64 + arow] = av.x;
            As[(akq * 4 + 1) * 64 + arow] = av.y;
            As[(akq * 4 + 2) * 64 + arow] = av.z;
            As[(akq * 4 + 3) * 64 + arow] = av.w;
        }
        for (int i = tid; i < 1024; i += 256)
            ((float4*)Bs)[i] = *(const float4*)&W3[(k0 + (i >> 6)) * DIM + c0 + (i & 63) * 4];
        __syncthreads();
#pragma unroll
        for (int kk = 0; kk < 16; kk++) {
            const float* arow_p = &As[kk * 64 + rg * 8];
            float4 a0 = *(const float4*)arow_p;
            float4 a1 = *(const float4*)(arow_p + 4);
            u64 ap[8];
            ap[0] = pack2(a0.x, a0.x); ap[1] = pack2(a0.y, a0.y);
            ap[2] = pack2(a0.z, a0.z); ap[3] = pack2(a0.w, a0.w);
            ap[4] = pack2(a1.x, a1.x); ap[5] = pack2(a1.y, a1.y);
            ap[6] = pack2(a1.z, a1.z); ap[7] = pack2(a1.w, a1.w);
            ulonglong2 bv0 = *(const ulonglong2*)&Bs[kk * 256 + cg * 8];
            ulonglong2 bv1 = *(const ulonglong2*)&Bs[kk * 256 + cg * 8 + 4];
#pragma unroll
            for (int r = 0; r < 8; r++) {
                ffma2(acc2[r][0], ap[r], bv0.x);
                ffma2(acc2[r][1], ap[r], bv0.y);
                ffma2(acc2[r][2], ap[r], bv1.x);
                ffma2(acc2[r][3], ap[r], bv1.y);
            }
        }
    }

    int bbase = (r0 >> 13) * NSEG * DIM;
#pragma unroll
    for (int i = 0; i < 8; i++) {
        int row = r0 + rg * 8 + i;
        int sbase = bbase + lbls[rg * 8 + i] * DIM;
#pragma unroll
        for (int j = 0; j < 4; j++) {
            float lo, hi;
            unpack2(acc2[i][j], lo, hi);
            int cc = cg * 8 + 2 * j;
            float v0 = lo + b3s[cc];
            float v1 = hi + b3s[cc + 1];
            int col = c0 + cc;
            out[row * DIM + col]     = v0;
            out[row * DIM + col + 1] = v1;
            atomicAdd(&g_sums[sbase + col],     v0);
            atomicAdd(&g_sums[sbase + col + 1], v1);
        }
    }
}

__global__ void means_kernel() {
    int i = blockIdx.x * 256 + threadIdx.x;
    if (i >= BATCH * NSEG * DIM) return;
    g_means[i] = g_sums[i] / fmaxf(g_counts[i / DIM], 1.0f);
}

// ---------------- scalar 64x64 tiled GEMM for small GEMMs ----------------
struct GemmSmem { float As[64][17]; float Bs[16][64]; };

__device__ __forceinline__ void gemm_tile(const float* __restrict__ A,
                                          const float* __restrict__ Bm,
                                          int Kk, int Nn, int r0, int c0,
                                          GemmSmem* sm, float acc[4][4]) {
    int tid = threadIdx.x, tx = tid & 15, ty = tid >> 4;
    for (int k0 = 0; k0 < Kk; k0 += 16) {
        for (int i = tid; i < 1024; i += 256) {
            int r = i >> 4, kk = i & 15;
            sm->As[r][kk] = A[(r0 + r) * Kk + k0 + kk];
        }
        for (int i = tid; i < 1024; i += 256) {
            int kk = i >> 6, c = i & 63;
            sm->Bs[kk][c] = Bm[(k0 + kk) * Nn + c0 + c];
        }
        __syncthreads();
#pragma unroll
        for (int kk = 0; kk < 16; kk++) {
            float a0 = sm->As[ty * 4 + 0][kk];
            float a1 = sm->As[ty * 4 + 1][kk];
            float a2 = sm->As[ty * 4 + 2][kk];
            float a3 = sm->As[ty * 4 + 3][kk];
            float4 bf = *(const float4*)&sm->Bs[kk][tx * 4];
            acc[0][0] += a0 * bf.x; acc[0][1] += a0 * bf.y; acc[0][2] += a0 * bf.z; acc[0][3] += a0 * bf.w;
            acc[1][0] += a1 * bf.x; acc[1][1] += a1 * bf.y; acc[1][2] += a1 * bf.z; acc[1][3] += a1 * bf.w;
            acc[2][0] += a2 * bf.x; acc[2][1] += a2 * bf.y; acc[2][2] += a2 * bf.z; acc[2][3] += a2 * bf.w;
            acc[3][0] += a3 * bf.x; acc[3][1] += a3 * bf.y; acc[3][2] += a3 * bf.z; acc[3][3] += a3 * bf.w;
        }
        __syncthreads();
    }
}

__global__ void gemm_a_kernel(const float* __restrict__ Wa, const float* __restrict__ ba) {
    __shared__ GemmSmem sm;
    int r0 = blockIdx.y * 64, c0 = blockIdx.x * 64;
    float acc[4][4];
#pragma unroll
    for (int i = 0; i < 4; i++)
#pragma unroll
        for (int j = 0; j < 4; j++) acc[i][j] = 0.0f;
    gemm_tile(g_means, Wa, DIM, DIM, r0, c0, &sm, acc);
    int tid = threadIdx.x, tx = tid & 15, ty = tid >> 4;
#pragma unroll
    for (int i = 0; i < 4; i++)
#pragma unroll
        for (int j = 0; j < 4; j++) {
            int row = r0 + ty * 4 + i, col = c0 + tx * 4 + j;
            g_lin1[row * DIM + col] = acc[i][j] + ba[col];
        }
}

__global__ void ln_relu_kernel(const float* __restrict__ lng, const float* __restrict__ lnb) {
    int row = blockIdx.x, tid = threadIdx.x;
    __shared__ float sh[8];
    const float* a = &g_lin1[row * DIM];
    float s = 0.0f;
    for (int c = tid; c < DIM; c += 256) s += a[c];
#pragma unroll
    for (int o = 16; o > 0; o >>= 1) s += __shfl_xor_sync(0xffffffffu, s, o);
    if ((tid & 31) == 0) sh[tid >> 5] = s;
    __syncthreads();
    float mu = 0.0f;
#pragma unroll
    for (int w = 0; w < 8; w++) mu += sh[w];
    mu *= (1.0f / DIM);
    __syncthreads();
    float vs = 0.0f;
    for (int c = tid; c < DIM; c += 256) { float d = a[c] - mu; vs += d * d; }
#pragma unroll
    for (int o = 16; o > 0; o >>= 1) vs += __shfl_xor_sync(0xffffffffu, vs, o);
    if ((tid & 31) == 0) sh[tid >> 5] = vs;
    __syncthreads();
    float var = 0.0f;
#pragma unroll
    for (int w = 0; w < 8; w++) var += sh[w];
    var *= (1.0f / DIM);
    float rstd = rsqrtf(var + 1e-5f);
    for (int c = tid; c < DIM; c += 256) {
        float x = (a[c] - mu) * rstd * lng[c] + lnb[c];
        g_lnr[row * DIM + c] = fmaxf(x, 0.0f);
    }
}

__global__ void gemm_b_kernel(const float* __restrict__ Wb, const float* __restrict__ bb) {
    __shared__ GemmSmem sm;
    int r0 = blockIdx.y * 64, c0 = blockIdx.x * 64;
    float acc[4][4];
#pragma unroll
    for (int i = 0; i < 4; i++)
#pragma unroll
        for (int j = 0; j < 4; j++) acc[i][j] = 0.0f;
    gemm_tile(g_lnr, Wb, DIM, DIM, r0, c0, &sm, acc);
    int tid = threadIdx.x, tx = tid & 15, ty = tid >> 4;
#pragma unroll
    for (int i = 0; i < 4; i++)
#pragma unroll
        for (int j = 0; j < 4; j++) {
            int row = r0 + ty * 4 + i, col = c0 + tx * 4 + j;
            g_agg[row * DIM + col] = acc[i][j] + bb[col];
        }
}

__global__ void mix_kernel(const int* __restrict__ labels, float* __restrict__ out) {
    int row = blockIdx.y;
    int col = blockIdx.x * 256 + threadIdx.x;
    int lbl = labels[row];
    int bs = (row >> 13) * NSEG + lbl;
    float pc = out[row * DIM + col];
    float res = pc;
    if (g_counts[bs] >= 2.0f)
        res = 0.8f * pc + 0.2f * g_agg[bs * DIM + col];
    out[row * DIM + col] = res;
}

// ---------------- launch ----------------
extern "C" void kernel_launch(void* const* d_in, const int* in_sizes, int n_in,
                              void* d_out, int out_size) {
    const float* coords = (const float*)d_in[0];
    const int*   labels = (const int*)d_in[1];
    const float* W1 = (const float*)d_in[2];
    const float* b1 = (const float*)d_in[3];
    const float* W2 = (const float*)d_in[4];
    const float* b2 = (const float*)d_in[5];
    const float* W3 = (const float*)d_in[6];
    const float* b3 = (const float*)d_in[7];
    const float* Wa = (const float*)d_in[8];
    const float* ba = (const float*)d_in[9];
    const float* lng = (const float*)d_in[10];
    const float* lnb = (const float*)d_in[11];
    const float* Wb = (const float*)d_in[12];
    const float* bb = (const float*)d_in[13];
    float* out = (float*)d_out;

    const int DSMEM = 81920;
    static bool attr_set = false;
    if (!attr_set) {
        cudaFuncSetAttribute(mlp12h_kernel,
                             cudaFuncAttributeMaxDynamicSharedMemorySize, DSMEM);
        attr_set = true;
    }

    prep_kernel<<<(BATCH * NSEG * DIM + 255) / 256, 256>>>(coords);
    count_kernel<<<(BATCH * NPTS + 255) / 256, 256>>>(labels);
    w2split_kernel<<<(H2DIM * H1DIM + 255) / 256, 256>>>(W2);
    knn_kernel<<<dim3(NPTS / 8, BATCH), 256>>>();
    mlp12h_kernel<<<BATCH * NPTS / 8, 512, DSMEM>>>(W1, b1, b2);
    gemm_pc_kernel<<<dim3(DIM / 256, BATCH * NPTS / 64), 256>>>(W3, b3, labels, out);
    means_kernel<<<(BATCH * NSEG * DIM + 255) / 256, 256>>>();
    gemm_a_kernel<<<dim3(DIM / 64, BATCH * NSEG / 64), 256>>>(Wa, ba);
    ln_relu_kernel<<<BATCH * NSEG, 256>>>(lng, lnb);
    gemm_b_kernel<<<dim3(DIM / 64, BATCH * NSEG / 64), 256>>>(Wb, bb);
    mix_kernel<<<dim3(DIM / 256, BATCH * NPTS), 256>>>(labels, out);
}

// round 17
// speedup vs baseline: 1.1536x; 1.1536x over previous
#include <cuda_runtime.h>
#include <cuda_bf16.h>
#include <math.h>
#include <float.h>

#define BATCH 2
#define NPTS  8192
#define KNB   16
#define NSEG  256
#define DIM   768
#define H1DIM 128
#define H2DIM 256

typedef unsigned long long u64;

// ---------------- f32x2 helpers (gemm_pc) ----------------
__device__ __forceinline__ void ffma2(u64& d, u64 a, u64 b) {
    asm("fma.rn.f32x2 %0, %1, %2, %0;" : "+l"(d) : "l"(a), "l"(b));
}
__device__ __forceinline__ u64 pack2(float lo, float hi) {
    u64 r; asm("mov.b64 %0, {%1, %2};" : "=l"(r) : "f"(lo), "f"(hi)); return r;
}
__device__ __forceinline__ void unpack2(u64 v, float& lo, float& hi) {
    asm("mov.b64 {%0, %1}, %2;" : "=f"(lo), "=f"(hi) : "l"(v));
}

// ---------------- HMMA helpers ----------------
__device__ __forceinline__ unsigned smem_u32(const void* p) {
    unsigned a;
    asm("{ .reg .u64 t; cvta.to.shared.u64 t, %1; cvt.u32.u64 %0, t; }" : "=r"(a) : "l"(p));
    return a;
}
__device__ __forceinline__ void ldsm4(unsigned addr, unsigned r[4]) {
    asm volatile("ldmatrix.sync.aligned.m8n8.x4.shared.b16 {%0,%1,%2,%3}, [%4];"
                 : "=r"(r[0]), "=r"(r[1]), "=r"(r[2]), "=r"(r[3]) : "r"(addr));
}
__device__ __forceinline__ void mma16816(float d[4], const unsigned a[4],
                                         unsigned b0, unsigned b1) {
    asm volatile(
        "mma.sync.aligned.m16n8k16.row.col.f32.bf16.bf16.f32 "
        "{%0,%1,%2,%3},{%4,%5,%6,%7},{%8,%9},{%0,%1,%2,%3};"
        : "+f"(d[0]), "+f"(d[1]), "+f"(d[2]), "+f"(d[3])
        : "r"(a[0]), "r"(a[1]), "r"(a[2]), "r"(a[3]), "r"(b0), "r"(b1));
}

// ---------------- device scratch ----------------
static __device__ float4 g_c4[BATCH * NPTS];
static __device__ int    g_idx[BATCH * NPTS * KNB];
static __device__ __align__(16) float g_hbar[BATCH * NPTS * H2DIM];
static __device__ float  g_sums[BATCH * NSEG * DIM];
static __device__ float  g_counts[BATCH * NSEG];
static __device__ float  g_means[BATCH * NSEG * DIM];
static __device__ float  g_lin1[BATCH * NSEG * DIM];
static __device__ float  g_lnr[BATCH * NSEG * DIM];
static __device__ float  g_agg[BATCH * NSEG * DIM];
// W2 hi/lo as the EXACT smem image: [n][128k] bf16, 256B rows, 16B-chunk XOR swizzle
static __device__ __align__(16) __nv_bfloat16 g_w2h[H2DIM * H1DIM];
static __device__ __align__(16) __nv_bfloat16 g_w2l[H2DIM * H1DIM];

// ---------------- prep kernels ----------------
__global__ void prep_kernel(const float* __restrict__ coords) {
    int i = blockIdx.x * 256 + threadIdx.x;
    if (i < BATCH * NSEG * DIM) g_sums[i] = 0.0f;
    if (i < BATCH * NSEG) g_counts[i] = 0.0f;
    if (i < BATCH * NPTS) {
        float x = coords[3 * i + 0];
        float y = coords[3 * i + 1];
        float z = coords[3 * i + 2];
        g_c4[i] = make_float4(x, y, z, x * x + y * y + z * z);
    }
}

__global__ void count_kernel(const int* __restrict__ labels) {
    int i = blockIdx.x * 256 + threadIdx.x;
    if (i >= BATCH * NPTS) return;
    atomicAdd(&g_counts[(i >> 13) * NSEG + labels[i]], 1.0f);
}

// split W2 (fp32 [k][n]) into bf16 hi/lo laid out as the swizzled smem image:
// byte offset for (n,k) = n*256 + (((k>>3) ^ (n&7)) << 4) + (k&7)*2
__global__ void w2split_kernel(const float* __restrict__ W2) {
    int i = blockIdx.x * 256 + threadIdx.x;
    if (i >= H2DIM * H1DIM) return;
    int n = i >> 7, k = i & 127;
    float v = W2[k * H2DIM + n];
    __nv_bfloat16 h = __float2bfloat16(v);
    __nv_bfloat16 l = __float2bfloat16(v - __bfloat162float(h));
    unsigned idx = ((unsigned)n * 256u + ((((unsigned)k >> 3) ^ ((unsigned)n & 7u)) << 4)
                    + ((unsigned)k & 7u) * 2u) >> 1;
    g_w2h[idx] = h;
    g_w2l[idx] = l;
}

// ---------------- KNN: warp-cooperative sorted queue + ballot collect ----------------
__global__ void knn_kernel() {
    __shared__ float4 tile[2048];
    int b = blockIdx.y;
    int warp = threadIdx.x >> 5;
    int lane = threadIdx.x & 31;
    int q = blockIdx.x * 8 + warp;

    float4 qc = g_c4[b * NPTS + q];
    float ax = -2.0f * qc.x, ay = -2.0f * qc.y, az = -2.0f * qc.z;

    const float INF  = __int_as_float(0x7f800000);
    const float NINF = __int_as_float(0xff800000);
    float S = INF;
    float thresh = INF;

    for (int t = 0; t < 4; t++) {
        __syncthreads();
        for (int i = threadIdx.x; i < 2048; i += 256)
            tile[i] = g_c4[b * NPTS + t * 2048 + i];
        __syncthreads();
#pragma unroll 4
        for (int it = 0; it < 64; it++) {
            float4 c = tile[it * 32 + lane];
            float key = fmaf(ax, c.x, fmaf(ay, c.y, fmaf(az, c.z, c.w)));
            unsigned ball = __ballot_sync(0xffffffffu, key < thresh);
            while (ball) {
                int src = __ffs(ball) - 1;
                ball &= ball - 1;
                float k = __shfl_sync(0xffffffffu, key, src);
                float up = __shfl_up_sync(0xffffffffu, S, 1);
                if (lane == 0) up = NINF;
                S = (S < k) ? S : fmaxf(k, up);
                thresh = __shfl_sync(0xffffffffu, S, 15);
            }
        }
    }

    int cnt = 0;
    int base = (b * NPTS + q) * KNB;
    for (int t = 0; t < 4; t++) {
        __syncthreads();
        for (int i = threadIdx.x; i < 2048; i += 256)
            tile[i] = g_c4[b * NPTS + t * 2048 + i];
        __syncthreads();
#pragma unroll 4
        for (int it = 0; it < 64; it++) {
            float4 c = tile[it * 32 + lane];
            float key = fmaf(ax, c.x, fmaf(ay, c.y, fmaf(az, c.z, c.w)));
            bool p = (key <= thresh);
            unsigned ball = __ballot_sync(0xffffffffu, p);
            if (p) {
                int pos = cnt + __popc(ball & ((1u << lane) - 1u));
                if (pos < KNB) g_idx[base + pos] = t * 2048 + it * 32 + lane;
            }
            cnt += __popc(ball);
        }
    }
}

// ---------------- mlp12 via HMMA, conflict-free swizzled smem ----------------
// block = 512 threads (16 warps), 8 points = 128 rows; cols = 256; K = 128.
// warp: rg = wid&7 (rows rg*16..+15 = one point), cg = wid>>3 (cols cg*128..+127).
// dynamic smem: h1h 32K | h1l 32K | w2h 64K | w2l 64K = 196608 B. All tiles are
// [row][128k] bf16 with 256B rows; 16B chunk c stored at (c ^ (row&7)).
__global__ void __launch_bounds__(512, 1)
mlp12h_kernel(const float* __restrict__ W1, const float* __restrict__ b1,
              const float* __restrict__ b2) {
    extern __shared__ __align__(16) char dsm[];
    char* h1h = dsm;
    char* h1l = dsm + 32768;
    char* w2h = dsm + 65536;
    char* w2l = dsm + 131072;
    __shared__ float w1s[7 * H1DIM];
    __shared__ float b1s[H1DIM];
    __shared__ float b2s[H2DIM];

    int tid = threadIdx.x;
    int wid = tid >> 5;
    int lane = tid & 31;
    int blk = blockIdx.x;
    int rg = wid & 7, cg = wid >> 3;

    for (int i = tid; i < 7 * H1DIM; i += 512) w1s[i] = W1[i];
    if (tid < H1DIM) b1s[tid] = b1[tid];
    if (tid < H2DIM) b2s[tid] = b2[tid];
    // stage full W2 hi/lo (preswizzled image, flat copy)
    for (int i = tid; i < 4096; i += 512) {
        ((uint4*)w2h)[i] = ((const uint4*)g_w2h)[i];
        ((uint4*)w2l)[i] = ((const uint4*)g_w2l)[i];
    }
    __syncthreads();

    // ---- phase 1: features + layer1 -> bf16 hi/lo swizzled smem ----
    {
        int row = tid >> 2;          // 0..127
        int qq  = tid & 3;           // channel quarter (32 ch = chunks qq*4..qq*4+3)
        int pg  = blk * 8 + (row >> 4);
        int bb  = pg >> 13;
        int k   = row & 15;
        int nb  = g_idx[pg * KNB + k];
        float4 sc = g_c4[pg];
        float4 nc = g_c4[bb * NPTS + nb];
        float dx = nc.x - sc.x, dy = nc.y - sc.y, dz = nc.z - sc.z;
        float f0 = sqrtf(dx * dx + dy * dy + dz * dz);
        float f4 = atan2f(dy, dx);
        float f5 = atan2f(dz, dx);
        float f6 = atan2f(dz, dy);
        unsigned rsw = (unsigned)(row & 7);
#pragma unroll
        for (int j = 0; j < 4; j++) {
            unsigned hh[4], ll[4];
#pragma unroll
            for (int tt = 0; tt < 4; tt++) {
                int c = qq * 32 + j * 8 + 2 * tt;
                float a0 = b1s[c], a1 = b1s[c + 1];
                a0 = fmaf(f0, w1s[c], a0);               a1 = fmaf(f0, w1s[c + 1], a1);
                a0 = fmaf(dx, w1s[H1DIM + c], a0);       a1 = fmaf(dx, w1s[H1DIM + c + 1], a1);
                a0 = fmaf(dy, w1s[2 * H1DIM + c], a0);   a1 = fmaf(dy, w1s[2 * H1DIM + c + 1], a1);
                a0 = fmaf(dz, w1s[3 * H1DIM + c], a0);   a1 = fmaf(dz, w1s[3 * H1DIM + c + 1], a1);
                a0 = fmaf(f4, w1s[4 * H1DIM + c], a0);   a1 = fmaf(f4, w1s[4 * H1DIM + c + 1], a1);
                a0 = fmaf(f5, w1s[5 * H1DIM + c], a0);   a1 = fmaf(f5, w1s[5 * H1DIM + c + 1], a1);
                a0 = fmaf(f6, w1s[6 * H1DIM + c], a0);   a1 = fmaf(f6, w1s[6 * H1DIM + c + 1], a1);
                a0 = fmaxf(a0, 0.0f); a1 = fmaxf(a1, 0.0f);
                __nv_bfloat16 h0 = __float2bfloat16(a0), h1 = __float2bfloat16(a1);
                float r0 = a0 - __bfloat162float(h0), r1 = a1 - __bfloat162float(h1);
                __nv_bfloat16 l0 = __float2bfloat16(r0), l1 = __float2bfloat16(r1);
                hh[tt] = ((unsigned)__bfloat16_as_ushort(h1) << 16) | (unsigned)__bfloat16_as_ushort(h0);
                ll[tt] = ((unsigned)__bfloat16_as_ushort(l1) << 16) | (unsigned)__bfloat16_as_ushort(l0);
            }
            unsigned chunk = (unsigned)(qq * 4 + j) ^ rsw;
            unsigned off = (unsigned)row * 256u + (chunk << 4);
            *(uint4*)(h1h + off) = make_uint4(hh[0], hh[1], hh[2], hh[3]);
            *(uint4*)(h1l + off) = make_uint4(ll[0], ll[1], ll[2], ll[3]);
        }
    }
    __syncthreads();

    // ---- phase 2: D = Ah*Bh + Ah*Bl + Al*Bh over K=128, no syncs ----
    float d[16][4];
#pragma unroll
    for (int nt = 0; nt < 16; nt++)
#pragma unroll
        for (int j = 0; j < 4; j++) d[nt][j] = 0.0f;

    unsigned h1h_b = smem_u32(h1h), h1l_b = smem_u32(h1l);
    unsigned w2h_b = smem_u32(w2h), w2l_b = smem_u32(w2l);

    unsigned arow = (unsigned)(rg * 16 + (lane & 15));
    unsigned ack  = (unsigned)(lane >> 4);            // + ks*2
    unsigned abase = arow * 256u;
    unsigned arsw  = arow & 7u;

    unsigned brow0 = (unsigned)(cg * 128 + (lane & 7) + ((lane >> 4) << 3));
    unsigned bck   = (unsigned)((lane >> 3) & 1);     // + ks*2

    for (int ks = 0; ks < 8; ks++) {
        unsigned ah[4], al[4];
        unsigned ac = ((unsigned)(ks * 2) + ack) ^ arsw;
        unsigned aaddr = abase + (ac << 4);
        ldsm4(h1h_b + aaddr, ah);
        ldsm4(h1l_b + aaddr, al);

#pragma unroll
        for (int i = 0; i < 8; i++) {
            unsigned brow = brow0 + (unsigned)(i * 16);
            unsigned bc = ((unsigned)(ks * 2) + bck) ^ (brow & 7u);
            unsigned baddr = brow * 256u + (bc << 4);
            unsigned bh[4], bl[4];
            ldsm4(w2h_b + baddr, bh);
            ldsm4(w2l_b + baddr, bl);
            mma16816(d[2 * i],     ah, bh[0], bh[1]);
            mma16816(d[2 * i],     ah, bl[0], bl[1]);
            mma16816(d[2 * i],     al, bh[0], bh[1]);
            mma16816(d[2 * i + 1], ah, bh[2], bh[3]);
            mma16816(d[2 * i + 1], ah, bl[2], bl[3]);
            mma16816(d[2 * i + 1], al, bh[2], bh[3]);
        }
    }

    // ---- epilogue: bias + relu, mean over the point's 16 rows ----
    int p = blk * 8 + rg;
    const float inv16 = 1.0f / 16.0f;
#pragma unroll
    for (int nt = 0; nt < 16; nt++) {
        int ncol = cg * 128 + nt * 8 + 2 * (lane & 3);
        float bv0 = b2s[ncol], bv1 = b2s[ncol + 1];
        float s0 = fmaxf(d[nt][0] + bv0, 0.0f) + fmaxf(d[nt][2] + bv0, 0.0f);
        float s1 = fmaxf(d[nt][1] + bv1, 0.0f) + fmaxf(d[nt][3] + bv1, 0.0f);
        s0 += __shfl_xor_sync(0xffffffffu, s0, 4);
        s0 += __shfl_xor_sync(0xffffffffu, s0, 8);
        s0 += __shfl_xor_sync(0xffffffffu, s0, 16);
        s1 += __shfl_xor_sync(0xffffffffu, s1, 4);
        s1 += __shfl_xor_sync(0xffffffffu, s1, 8);
        s1 += __shfl_xor_sync(0xffffffffu, s1, 16);
        if (lane < 4) {
            int col = cg * 128 + nt * 8 + 2 * lane;
            g_hbar[p * H2DIM + col]     = s0 * inv16;
            g_hbar[p * H2DIM + col + 1] = s1 * inv16;
        }
    }
}

// ---------------- gemm_pc: pc = hbar @ W3 + b3, FFMA2 8x8, fused scatter ----------------
__global__ void __launch_bounds__(256, 2)
gemm_pc_kernel(const float* __restrict__ W3, const float* __restrict__ b3,
               const int* __restrict__ labels, float* __restrict__ out) {
    __shared__ __align__(16) float As[16 * 64];
    __shared__ __align__(16) float Bs[16 * 256];
    __shared__ int   lbls[64];
    __shared__ float b3s[256];
    int tid = threadIdx.x;
    int r0 = blockIdx.y * 64;
    int c0 = blockIdx.x * 256;

    if (tid < 64) lbls[tid] = labels[r0 + tid];
    b3s[tid] = b3[c0 + tid];

    int lane = tid & 31, w = tid >> 5;
    int rg  = lane >> 2;
    int cgl = lane & 3;
    int cg  = w * 4 + cgl;

    u64 acc2[8][4];
#pragma unroll
    for (int r = 0; r < 8; r++)
#pragma unroll
        for (int j = 0; j < 4; j++) acc2[r][j] = 0ull;

    int arow = tid & 63, akq = tid >> 6;
    for (int k0 = 0; k0 < H2DIM; k0 += 16) {
        __syncthreads();
        {
            float4 av = *(const float4*)&g_hbar[(r0 + arow) * H2DIM + k0 + akq * 4];
            As[(akq * 4 + 0) * 64 + arow] = av.x;
            As[(akq * 4 + 1) * 64 + arow] = av.y;
            As[(akq * 4 + 2) * 64 + arow] = av.z;
            As[(akq * 4 + 3) * 64 + arow] = av.w;
        }
        for (int i = tid; i < 1024; i += 256)
            ((float4*)Bs)[i] = *(const float4*)&W3[(k0 + (i >> 6)) * DIM + c0 + (i & 63) * 4];
        __syncthreads();
#pragma unroll
        for (int kk = 0; kk < 16; kk++) {
            const float* arow_p = &As[kk * 64 + rg * 8];
            float4 a0 = *(const float4*)arow_p;
            float4 a1 = *(const float4*)(arow_p + 4);
            u64 ap[8];
            ap[0] = pack2(a0.x, a0.x); ap[1] = pack2(a0.y, a0.y);
            ap[2] = pack2(a0.z, a0.z); ap[3] = pack2(a0.w, a0.w);
            ap[4] = pack2(a1.x, a1.x); ap[5] = pack2(a1.y, a1.y);
            ap[6] = pack2(a1.z, a1.z); ap[7] = pack2(a1.w, a1.w);
            ulonglong2 bv0 = *(const ulonglong2*)&Bs[kk * 256 + cg * 8];
            ulonglong2 bv1 = *(const ulonglong2*)&Bs[kk * 256 + cg * 8 + 4];
#pragma unroll
            for (int r = 0; r < 8; r++) {
                ffma2(acc2[r][0], ap[r], bv0.x);
                ffma2(acc2[r][1], ap[r], bv0.y);
                ffma2(acc2[r][2], ap[r], bv1.x);
                ffma2(acc2[r][3], ap[r], bv1.y);
            }
        }
    }

    int bbase = (r0 >> 13) * NSEG * DIM;
#pragma unroll
    for (int i = 0; i < 8; i++) {
        int row = r0 + rg * 8 + i;
        int sbase = bbase + lbls[rg * 8 + i] * DIM;
#pragma unroll
        for (int j = 0; j < 4; j++) {
            float lo, hi;
            unpack2(acc2[i][j], lo, hi);
            int cc = cg * 8 + 2 * j;
            float v0 = lo + b3s[cc];
            float v1 = hi + b3s[cc + 1];
            int col = c0 + cc;
            out[row * DIM + col]     = v0;
            out[row * DIM + col + 1] = v1;
            atomicAdd(&g_sums[sbase + col],     v0);
            atomicAdd(&g_sums[sbase + col + 1], v1);
        }
    }
}

__global__ void means_kernel() {
    int i = blockIdx.x * 256 + threadIdx.x;
    if (i >= BATCH * NSEG * DIM) return;
    g_means[i] = g_sums[i] / fmaxf(g_counts[i / DIM], 1.0f);
}

// ---------------- scalar 64x64 tiled GEMM for small GEMMs ----------------
struct GemmSmem { float As[64][17]; float Bs[16][64]; };

__device__ __forceinline__ void gemm_tile(const float* __restrict__ A,
                                          const float* __restrict__ Bm,
                                          int Kk, int Nn, int r0, int c0,
                                          GemmSmem* sm, float acc[4][4]) {
    int tid = threadIdx.x, tx = tid & 15, ty = tid >> 4;
    for (int k0 = 0; k0 < Kk; k0 += 16) {
        for (int i = tid; i < 1024; i += 256) {
            int r = i >> 4, kk = i & 15;
            sm->As[r][kk] = A[(r0 + r) * Kk + k0 + kk];
        }
        for (int i = tid; i < 1024; i += 256) {
            int kk = i >> 6, c = i & 63;
            sm->Bs[kk][c] = Bm[(k0 + kk) * Nn + c0 + c];
        }
        __syncthreads();
#pragma unroll
        for (int kk = 0; kk < 16; kk++) {
            float a0 = sm->As[ty * 4 + 0][kk];
            float a1 = sm->As[ty * 4 + 1][kk];
            float a2 = sm->As[ty * 4 + 2][kk];
            float a3 = sm->As[ty * 4 + 3][kk];
            float4 bf = *(const float4*)&sm->Bs[kk][tx * 4];
            acc[0][0] += a0 * bf.x; acc[0][1] += a0 * bf.y; acc[0][2] += a0 * bf.z; acc[0][3] += a0 * bf.w;
            acc[1][0] += a1 * bf.x; acc[1][1] += a1 * bf.y; acc[1][2] += a1 * bf.z; acc[1][3] += a1 * bf.w;
            acc[2][0] += a2 * bf.x; acc[2][1] += a2 * bf.y; acc[2][2] += a2 * bf.z; acc[2][3] += a2 * bf.w;
            acc[3][0] += a3 * bf.x; acc[3][1] += a3 * bf.y; acc[3][2] += a3 * bf.z; acc[3][3] += a3 * bf.w;
        }
        __syncthreads();
    }
}

__global__ void gemm_a_kernel(const float* __restrict__ Wa, const float* __restrict__ ba) {
    __shared__ GemmSmem sm;
    int r0 = blockIdx.y * 64, c0 = blockIdx.x * 64;
    float acc[4][4];
#pragma unroll
    for (int i = 0; i < 4; i++)
#pragma unroll
        for (int j = 0; j < 4; j++) acc[i][j] = 0.0f;
    gemm_tile(g_means, Wa, DIM, DIM, r0, c0, &sm, acc);
    int tid = threadIdx.x, tx = tid & 15, ty = tid >> 4;
#pragma unroll
    for (int i = 0; i < 4; i++)
#pragma unroll
        for (int j = 0; j < 4; j++) {
            int row = r0 + ty * 4 + i, col = c0 + tx * 4 + j;
            g_lin1[row * DIM + col] = acc[i][j] + ba[col];
        }
}

__global__ void ln_relu_kernel(const float* __restrict__ lng, const float* __restrict__ lnb) {
    int row = blockIdx.x, tid = threadIdx.x;
    __shared__ float sh[8];
    const float* a = &g_lin1[row * DIM];
    float s = 0.0f;
    for (int c = tid; c < DIM; c += 256) s += a[c];
#pragma unroll
    for (int o = 16; o > 0; o >>= 1) s += __shfl_xor_sync(0xffffffffu, s, o);
    if ((tid & 31) == 0) sh[tid >> 5] = s;
    __syncthreads();
    float mu = 0.0f;
#pragma unroll
    for (int w = 0; w < 8; w++) mu += sh[w];
    mu *= (1.0f / DIM);
    __syncthreads();
    float vs = 0.0f;
    for (int c = tid; c < DIM; c += 256) { float d = a[c] - mu; vs += d * d; }
#pragma unroll
    for (int o = 16; o > 0; o >>= 1) vs += __shfl_xor_sync(0xffffffffu, vs, o);
    if ((tid & 31) == 0) sh[tid >> 5] = vs;
    __syncthreads();
    float var = 0.0f;
#pragma unroll
    for (int w = 0; w < 8; w++) var += sh[w];
    var *= (1.0f / DIM);
    float rstd = rsqrtf(var + 1e-5f);
    for (int c = tid; c < DIM; c += 256) {
        float x = (a[c] - mu) * rstd * lng[c] + lnb[c];
        g_lnr[row * DIM + c] = fmaxf(x, 0.0f);
    }
}

__global__ void gemm_b_kernel(const float* __restrict__ Wb, const float* __restrict__ bb) {
    __shared__ GemmSmem sm;
    int r0 = blockIdx.y * 64, c0 = blockIdx.x * 64;
    float acc[4][4];
#pragma unroll
    for (int i = 0; i < 4; i++)
#pragma unroll
        for (int j = 0; j < 4; j++) acc[i][j] = 0.0f;
    gemm_tile(g_lnr, Wb, DIM, DIM, r0, c0, &sm, acc);
    int tid = threadIdx.x, tx = tid & 15, ty = tid >> 4;
#pragma unroll
    for (int i = 0; i < 4; i++)
#pragma unroll
        for (int j = 0; j < 4; j++) {
            int row = r0 + ty * 4 + i, col = c0 + tx * 4 + j;
            g_agg[row * DIM + col] = acc[i][j] + bb[col];
        }
}

__global__ void mix_kernel(const int* __restrict__ labels, float* __restrict__ out) {
    int row = blockIdx.y;
    int col = blockIdx.x * 256 + threadIdx.x;
    int lbl = labels[row];
    int bs = (row >> 13) * NSEG + lbl;
    float pc = out[row * DIM + col];
    float res = pc;
    if (g_counts[bs] >= 2.0f)
        res = 0.8f * pc + 0.2f * g_agg[bs * DIM + col];
    out[row * DIM + col] = res;
}

// ---------------- launch ----------------
extern "C" void kernel_launch(void* const* d_in, const int* in_sizes, int n_in,
                              void* d_out, int out_size) {
    const float* coords = (const float*)d_in[0];
    const int*   labels = (const int*)d_in[1];
    const float* W1 = (const float*)d_in[2];
    const float* b1 = (const float*)d_in[3];
    const float* W2 = (const float*)d_in[4];
    const float* b2 = (const float*)d_in[5];
    const float* W3 = (const float*)d_in[6];
    const float* b3 = (const float*)d_in[7];
    const float* Wa = (const float*)d_in[8];
    const float* ba = (const float*)d_in[9];
    const float* lng = (const float*)d_in[10];
    const float* lnb = (const float*)d_in[11];
    const float* Wb = (const float*)d_in[12];
    const float* bb = (const float*)d_in[13];
    float* out = (float*)d_out;

    const int DSMEM = 196608;
    static bool attr_set = false;
    if (!attr_set) {
        cudaFuncSetAttribute(mlp12h_kernel,
                             cudaFuncAttributeMaxDynamicSharedMemorySize, DSMEM);
        attr_set = true;
    }

    prep_kernel<<<(BATCH * NSEG * DIM + 255) / 256, 256>>>(coords);
    count_kernel<<<(BATCH * NPTS + 255) / 256, 256>>>(labels);
    w2split_kernel<<<(H2DIM * H1DIM + 255) / 256, 256>>>(W2);
    knn_kernel<<<dim3(NPTS / 8, BATCH), 256>>>();
    mlp12h_kernel<<<BATCH * NPTS / 8, 512, DSMEM>>>(W1, b1, b2);
    gemm_pc_kernel<<<dim3(DIM / 256, BATCH * NPTS / 64), 256>>>(W3, b3, labels, out);
    means_kernel<<<(BATCH * NSEG * DIM + 255) / 256, 256>>>();
    gemm_a_kernel<<<dim3(DIM / 64, BATCH * NSEG / 64), 256>>>(Wa, ba);
    ln_relu_kernel<<<BATCH * NSEG, 256>>>(lng, lnb);
    gemm_b_kernel<<<dim3(DIM / 64, BATCH * NSEG / 64), 256>>>(Wb, bb);
    mix_kernel<<<dim3(DIM / 256, BATCH * NPTS), 256>>>(labels, out);
}